// round 5
// baseline (speedup 1.0000x reference)
#include <cuda_runtime.h>

#define NMAX 100000

// Scratch (allocation-free rule: __device__ globals). 16B-aligned for float4/red.v4.
__device__ __align__(16) float g_Y1[NMAX * 32];
__device__ __align__(16) float g_Z1[NMAX * 32];
__device__ __align__(16) float g_Y2[NMAX * 32];
__device__ __align__(16) float g_Z2[NMAX * 32];
__device__ float g_S[NMAX];
__device__ int   g_is64;   // 1 if edge_index is int64, 0 if int32

// ---------------------------------------------------------------------------
// K0: detect edge index width. For int64 (values < 2^31, little-endian) every
// odd 32-bit word is the zero high-half; for int32 odd words are node ids.
// ---------------------------------------------------------------------------
__global__ void k_detect(const int* __restrict__ ei_w, int nWords) {
    __shared__ int any_nonzero;
    if (threadIdx.x == 0) any_nonzero = 0;
    __syncthreads();
    // sample up to 2048 odd words
    int nz = 0;
    for (int i = threadIdx.x; i < 2048; i += blockDim.x) {
        int w = 2 * i + 1;
        if (w < nWords && ei_w[w] != 0) nz = 1;
    }
    if (nz) atomicOr(&any_nonzero, 1);
    __syncthreads();
    if (threadIdx.x == 0) g_is64 = any_nonzero ? 0 : 1;
}

__device__ __forceinline__ void load_edge(const int* __restrict__ ei, int nE,
                                          int e, int& src, int& dst) {
    if (g_is64) {
        const long long* p = (const long long*)ei;
        src = (int)p[e];
        dst = (int)p[(size_t)nE + e];
    } else {
        src = ei[e];
        dst = ei[nE + e];
    }
}

// ---------------------------------------------------------------------------
// K1: y1 = x @ w1a   (nN x 128) @ (128 x 32)  -> writes Y1 and Z1 (init = y1)
// 128 threads/block; warp w handles k in [32w,32w+32), weight slice in regs,
// x broadcast by shfl. Double-buffered partial tile: one barrier per node.
// ---------------------------------------------------------------------------
__global__ void k_proj1(const float* __restrict__ x,
                        const float* __restrict__ w1a, int nN) {
    const int lane = threadIdx.x & 31;
    const int wid  = threadIdx.x >> 5;   // 0..3
    float wreg[32];
#pragma unroll
    for (int k = 0; k < 32; ++k)
        wreg[k] = w1a[(wid * 32 + k) * 32 + lane];

    __shared__ float part[2][4][32];

    int buf = 0;
    for (int node = blockIdx.x; node < nN; node += gridDim.x) {
        float xv = x[(size_t)node * 128 + wid * 32 + lane];
        float acc = 0.f;
#pragma unroll
        for (int k = 0; k < 32; ++k)
            acc = fmaf(__shfl_sync(0xffffffffu, xv, k), wreg[k], acc);
        part[buf][wid][lane] = acc;
        __syncthreads();
        if (wid == 0) {
            float y = part[buf][0][lane] + part[buf][1][lane]
                    + part[buf][2][lane] + part[buf][3][lane];
            g_Y1[node * 32 + lane] = y;
            g_Z1[node * 32 + lane] = y;
        }
        buf ^= 1;
    }
}

// ---------------------------------------------------------------------------
// K2/K4: edge aggregation in 32 channels.
// 8 lanes per edge, each lane handles one float4 (16B) -> vector red to L2.
// ---------------------------------------------------------------------------
__global__ void k_edge32(const int* __restrict__ ei, int nE, int which) {
    int t = blockIdx.x * blockDim.x + threadIdx.x;
    int e = t >> 3;
    if (e >= nE) return;
    int r = t & 7;
    int src, dst;
    load_edge(ei, nE, e, src, dst);
    const float* __restrict__ Y = which ? g_Y2 : g_Y1;
    float* Z = which ? g_Z2 : g_Z1;
    float4 v = *(const float4*)(Y + (size_t)src * 32 + r * 4);
    float* p = Z + (size_t)dst * 32 + r * 4;
    asm volatile("red.global.add.v4.f32 [%0], {%1,%2,%3,%4};"
                 :: "l"(p), "f"(v.x), "f"(v.y), "f"(v.z), "f"(v.w)
                 : "memory");
}

// ---------------------------------------------------------------------------
// K3: per node: t = relu(z1 + b1a); h1 = t@w1b + b1b; y2 = h1@w2a
// Writes Y2 and Z2 (init = y2). Weight columns register-resident per lane.
// ---------------------------------------------------------------------------
__global__ void k_mlp1(const float* __restrict__ w1b, const float* __restrict__ b1a,
                       const float* __restrict__ b1b, const float* __restrict__ w2a,
                       int nN) {
    const int lane = threadIdx.x & 31;
    float wc1[32], wc2[32];
#pragma unroll
    for (int k = 0; k < 32; ++k) {
        wc1[k] = w1b[k * 32 + lane];
        wc2[k] = w2a[k * 32 + lane];
    }
    const float ba = b1a[lane];
    const float bb = b1b[lane];

    int gw = (blockIdx.x * blockDim.x + threadIdx.x) >> 5;
    int nw = (gridDim.x * blockDim.x) >> 5;
    for (int node = gw; node < nN; node += nw) {
        float z  = g_Z1[node * 32 + lane];
        float tt = fmaxf(z + ba, 0.f);
        float acc = bb;
#pragma unroll
        for (int k = 0; k < 32; ++k)
            acc = fmaf(__shfl_sync(0xffffffffu, tt, k), wc1[k], acc);
        float h1 = acc;
        float acc2 = 0.f;
#pragma unroll
        for (int k = 0; k < 32; ++k)
            acc2 = fmaf(__shfl_sync(0xffffffffu, h1, k), wc2[k], acc2);
        g_Y2[node * 32 + lane] = acc2;
        g_Z2[node * 32 + lane] = acc2;
    }
}

// ---------------------------------------------------------------------------
// K5: per node: t = relu(z2 + b2a); h2 = t@w2b + b2b; s = h2 . w3
// Writes S[node] = s and out[node] = s + b3  (out fully initialized here).
// ---------------------------------------------------------------------------
__global__ void k_mlp2(const float* __restrict__ w2b, const float* __restrict__ b2a,
                       const float* __restrict__ b2b, const float* __restrict__ w3,
                       const float* __restrict__ b3, float* __restrict__ out, int nN) {
    const int lane = threadIdx.x & 31;
    float wc[32];
#pragma unroll
    for (int k = 0; k < 32; ++k)
        wc[k] = w2b[k * 32 + lane];
    const float ba  = b2a[lane];
    const float bb  = b2b[lane];
    const float w3l = w3[lane];
    const float b3v = b3[0];

    int gw = (blockIdx.x * blockDim.x + threadIdx.x) >> 5;
    int nw = (gridDim.x * blockDim.x) >> 5;
    for (int node = gw; node < nN; node += nw) {
        float z  = g_Z2[node * 32 + lane];
        float tt = fmaxf(z + ba, 0.f);
        float acc = bb;
#pragma unroll
        for (int k = 0; k < 32; ++k)
            acc = fmaf(__shfl_sync(0xffffffffu, tt, k), wc[k], acc);
        float sp = acc * w3l;
#pragma unroll
        for (int o = 16; o > 0; o >>= 1)
            sp += __shfl_xor_sync(0xffffffffu, sp, o);
        if (lane == 0) {
            g_S[node] = sp;
            out[node] = sp + b3v;
        }
    }
}

// ---------------------------------------------------------------------------
// K6: scalar edge aggregation for conv3: out[dst] += s[src]
// ---------------------------------------------------------------------------
__global__ void k_edge1(const int* __restrict__ ei, int nE,
                        float* __restrict__ out) {
    int e = blockIdx.x * blockDim.x + threadIdx.x;
    if (e >= nE) return;
    int src, dst;
    load_edge(ei, nE, e, src, dst);
    atomicAdd(out + dst, g_S[src]);
}

// ---------------------------------------------------------------------------
extern "C" void kernel_launch(void* const* d_in, const int* in_sizes, int n_in,
                              void* d_out, int out_size) {
    const float* x   = (const float*)d_in[0];
    const int*   ei  = (const int*)d_in[1];
    const float* w1a = (const float*)d_in[2];
    const float* b1a = (const float*)d_in[3];
    const float* w1b = (const float*)d_in[4];
    const float* b1b = (const float*)d_in[5];
    const float* w2a = (const float*)d_in[6];
    const float* b2a = (const float*)d_in[7];
    const float* w2b = (const float*)d_in[8];
    const float* b2b = (const float*)d_in[9];
    const float* w3  = (const float*)d_in[10];
    const float* b3  = (const float*)d_in[11];

    int nN = in_sizes[0] / 128;
    int nE = in_sizes[1] / 2;   // element count of edge_index / 2, dtype-independent
    float* out = (float*)d_out;

    // detect int32 vs int64 edge indices (JAX x64-disabled default -> int32)
    k_detect<<<1, 256>>>(ei, 2 * nE);
    // conv1: project 128->32 first (aggregation commutes with the linear map)
    k_proj1<<<4736, 128>>>(x, w1a, nN);
    k_edge32<<<((size_t)nE * 8 + 255) / 256, 256>>>(ei, nE, 0);
    // conv1 MLP tail + conv2 first linear (projection before aggregation again)
    k_mlp1<<<1184, 256>>>(w1b, b1a, b1b, w2a, nN);
    k_edge32<<<((size_t)nE * 8 + 255) / 256, 256>>>(ei, nE, 1);
    // conv2 MLP tail + conv3 linear (project to scalar before aggregation)
    k_mlp2<<<1184, 256>>>(w2b, b2a, b2b, w3, b3, out, nN);
    k_edge1<<<(nE + 255) / 256, 256>>>(ei, nE, out);
}

// round 6
// speedup vs baseline: 1.1701x; 1.1701x over previous
#include <cuda_runtime.h>

#define NMAX 100000

// Scratch (allocation-free rule: __device__ globals). 16B-aligned for float4/red.v4.
__device__ __align__(16) float g_Y1[NMAX * 32];
__device__ __align__(16) float g_Z1[NMAX * 32];
__device__ __align__(16) float g_Y2[NMAX * 32];
__device__ __align__(16) float g_Z2[NMAX * 32];
__device__ float g_S[NMAX];
__device__ int   g_is64;            // 1 if edge_index is int64, 0 if int32
// Folded weights (consecutive linears with no ReLU between them):
__device__ float g_W12[32 * 32];    // w1b @ w2a
__device__ float g_b12[32];         // b1b @ w2a
__device__ float g_w23[32];         // w2b @ w3
__device__ float g_c23;             // b2b . w3

// ---------------------------------------------------------------------------
// K0: dtype detect (int64 odd words are zero high-halves) + weight folding.
// ---------------------------------------------------------------------------
__global__ void k_init(const int* __restrict__ ei_w, int nWords,
                       const float* __restrict__ w1b, const float* __restrict__ b1b,
                       const float* __restrict__ w2a, const float* __restrict__ w2b,
                       const float* __restrict__ b2b, const float* __restrict__ w3) {
    __shared__ int any_nonzero;
    int tid = threadIdx.x;
    if (tid == 0) any_nonzero = 0;
    __syncthreads();
    int nz = 0;
    for (int i = tid; i < 2048; i += blockDim.x) {
        int w = 2 * i + 1;
        if (w < nWords && ei_w[w] != 0) nz = 1;
    }
    if (nz) atomicOr(&any_nonzero, 1);
    __syncthreads();
    if (tid == 0) g_is64 = any_nonzero ? 0 : 1;

    // W12[k][o] = sum_j w1b[k][j] * w2a[j][o]   (1024 threads: k=tid>>5, o=tid&31)
    int k = tid >> 5, o = tid & 31;
    float acc = 0.f;
#pragma unroll
    for (int j = 0; j < 32; ++j)
        acc = fmaf(w1b[k * 32 + j], w2a[j * 32 + o], acc);
    g_W12[k * 32 + o] = acc;

    if (tid < 32) {
        float b = 0.f, w = 0.f;
#pragma unroll
        for (int j = 0; j < 32; ++j) {
            b = fmaf(b1b[j], w2a[j * 32 + tid], b);   // b12[o]
            w = fmaf(w2b[tid * 32 + j], w3[j], w);    // w23[k]
        }
        g_b12[tid] = b;
        g_w23[tid] = w;
    }
    if (tid == 0) {
        float c = 0.f;
#pragma unroll
        for (int j = 0; j < 32; ++j) c = fmaf(b2b[j], w3[j], c);
        g_c23 = c;
    }
}

__device__ __forceinline__ void load_edge(const int* __restrict__ ei, int nE,
                                          int e, int& src, int& dst) {
    if (g_is64) {
        const long long* p = (const long long*)ei;
        src = (int)p[e];
        dst = (int)p[(size_t)nE + e];
    } else {
        src = ei[e];
        dst = ei[nE + e];
    }
}

// ---------------------------------------------------------------------------
// K1: y1 = x @ w1a  (nN x 128)@(128 x 32). 4 warps/node, weight slice in regs,
// 4-way split accumulators (dep chain 8 deep), double-buffered combine.
// ---------------------------------------------------------------------------
__global__ __launch_bounds__(128, 8) void k_proj1(const float* __restrict__ x,
                        const float* __restrict__ w1a, int nN) {
    const int lane = threadIdx.x & 31;
    const int wid  = threadIdx.x >> 5;   // 0..3
    float wreg[32];
#pragma unroll
    for (int k = 0; k < 32; ++k)
        wreg[k] = w1a[(wid * 32 + k) * 32 + lane];

    __shared__ float part[2][4][32];

    int buf = 0;
    for (int node = blockIdx.x; node < nN; node += gridDim.x) {
        float xv = x[(size_t)node * 128 + wid * 32 + lane];
        float a0 = 0.f, a1 = 0.f, a2 = 0.f, a3 = 0.f;
#pragma unroll
        for (int k = 0; k < 32; k += 4) {
            a0 = fmaf(__shfl_sync(0xffffffffu, xv, k + 0), wreg[k + 0], a0);
            a1 = fmaf(__shfl_sync(0xffffffffu, xv, k + 1), wreg[k + 1], a1);
            a2 = fmaf(__shfl_sync(0xffffffffu, xv, k + 2), wreg[k + 2], a2);
            a3 = fmaf(__shfl_sync(0xffffffffu, xv, k + 3), wreg[k + 3], a3);
        }
        part[buf][wid][lane] = (a0 + a1) + (a2 + a3);
        __syncthreads();
        if (wid == 0) {
            float y = part[buf][0][lane] + part[buf][1][lane]
                    + part[buf][2][lane] + part[buf][3][lane];
            g_Y1[node * 32 + lane] = y;
            g_Z1[node * 32 + lane] = y;
        }
        buf ^= 1;
    }
}

// ---------------------------------------------------------------------------
// K2/K4: edge aggregation in 32 channels.
// 8 lanes per edge, each lane one float4 -> red.global.add.v4.f32.
// ---------------------------------------------------------------------------
__global__ void k_edge32(const int* __restrict__ ei, int nE, int which) {
    int t = blockIdx.x * blockDim.x + threadIdx.x;
    int e = t >> 3;
    if (e >= nE) return;
    int r = t & 7;
    int src, dst;
    load_edge(ei, nE, e, src, dst);
    const float* __restrict__ Y = which ? g_Y2 : g_Y1;
    float* Z = which ? g_Z2 : g_Z1;
    float4 v = *(const float4*)(Y + (size_t)src * 32 + r * 4);
    float* p = Z + (size_t)dst * 32 + r * 4;
    asm volatile("red.global.add.v4.f32 [%0], {%1,%2,%3,%4};"
                 :: "l"(p), "f"(v.x), "f"(v.y), "f"(v.z), "f"(v.w)
                 : "memory");
}

// ---------------------------------------------------------------------------
// K3: per node: y2 = relu(z1 + b1a) @ W12 + b12   (folded w1b@w2a).
// 2 nodes per warp iteration, 4-way split accumulators.
// ---------------------------------------------------------------------------
__global__ __launch_bounds__(256, 4) void k_mlp1(const float* __restrict__ b1a, int nN) {
    const int lane = threadIdx.x & 31;
    float wc[32];
#pragma unroll
    for (int k = 0; k < 32; ++k)
        wc[k] = g_W12[k * 32 + lane];
    const float ba = b1a[lane];
    const float bb = g_b12[lane];

    int gw = (blockIdx.x * blockDim.x + threadIdx.x) >> 5;
    int nw = (gridDim.x * blockDim.x) >> 5;
    for (int n0 = gw * 2; n0 < nN; n0 += nw * 2) {
        int n1 = n0 + 1;
        bool has1 = (n1 < nN);
        float z0 = g_Z1[n0 * 32 + lane];
        float z1 = has1 ? g_Z1[n1 * 32 + lane] : 0.f;
        float t0 = fmaxf(z0 + ba, 0.f);
        float t1 = fmaxf(z1 + ba, 0.f);
        float a00 = bb, a01 = 0.f, a02 = 0.f, a03 = 0.f;
        float a10 = bb, a11 = 0.f, a12 = 0.f, a13 = 0.f;
#pragma unroll
        for (int k = 0; k < 32; k += 4) {
            a00 = fmaf(__shfl_sync(0xffffffffu, t0, k + 0), wc[k + 0], a00);
            a10 = fmaf(__shfl_sync(0xffffffffu, t1, k + 0), wc[k + 0], a10);
            a01 = fmaf(__shfl_sync(0xffffffffu, t0, k + 1), wc[k + 1], a01);
            a11 = fmaf(__shfl_sync(0xffffffffu, t1, k + 1), wc[k + 1], a11);
            a02 = fmaf(__shfl_sync(0xffffffffu, t0, k + 2), wc[k + 2], a02);
            a12 = fmaf(__shfl_sync(0xffffffffu, t1, k + 2), wc[k + 2], a12);
            a03 = fmaf(__shfl_sync(0xffffffffu, t0, k + 3), wc[k + 3], a03);
            a13 = fmaf(__shfl_sync(0xffffffffu, t1, k + 3), wc[k + 3], a13);
        }
        float y0 = (a00 + a01) + (a02 + a03);
        g_Y2[n0 * 32 + lane] = y0;
        g_Z2[n0 * 32 + lane] = y0;
        if (has1) {
            float y1 = (a10 + a11) + (a12 + a13);
            g_Y2[n1 * 32 + lane] = y1;
            g_Z2[n1 * 32 + lane] = y1;
        }
    }
}

// ---------------------------------------------------------------------------
// K5: per node: s = relu(z2+b2a) . w23 + c23 (folded w2b@w3);
// S[node]=s, out[node]=s+b3.
// ---------------------------------------------------------------------------
__global__ __launch_bounds__(256, 8) void k_mlp2(const float* __restrict__ b2a,
                       const float* __restrict__ b3, float* __restrict__ out, int nN) {
    const int lane = threadIdx.x & 31;
    const float ba  = b2a[lane];
    const float wl  = g_w23[lane];
    const float c23 = g_c23;
    const float b3v = b3[0];

    int gw = (blockIdx.x * blockDim.x + threadIdx.x) >> 5;
    int nw = (gridDim.x * blockDim.x) >> 5;
    for (int node = gw; node < nN; node += nw) {
        float z  = g_Z2[node * 32 + lane];
        float sp = fmaxf(z + ba, 0.f) * wl;
#pragma unroll
        for (int o = 16; o > 0; o >>= 1)
            sp += __shfl_xor_sync(0xffffffffu, sp, o);
        if (lane == 0) {
            float s = sp + c23;
            g_S[node] = s;
            out[node] = s + b3v;
        }
    }
}

// ---------------------------------------------------------------------------
// K6: scalar edge aggregation for conv3: out[dst] += s[src]
// ---------------------------------------------------------------------------
__global__ void k_edge1(const int* __restrict__ ei, int nE,
                        float* __restrict__ out) {
    int e = blockIdx.x * blockDim.x + threadIdx.x;
    if (e >= nE) return;
    int src, dst;
    load_edge(ei, nE, e, src, dst);
    atomicAdd(out + dst, g_S[src]);
}

// ---------------------------------------------------------------------------
extern "C" void kernel_launch(void* const* d_in, const int* in_sizes, int n_in,
                              void* d_out, int out_size) {
    const float* x   = (const float*)d_in[0];
    const int*   ei  = (const int*)d_in[1];
    const float* w1a = (const float*)d_in[2];
    const float* b1a = (const float*)d_in[3];
    const float* w1b = (const float*)d_in[4];
    const float* b1b = (const float*)d_in[5];
    const float* w2a = (const float*)d_in[6];
    const float* b2a = (const float*)d_in[7];
    const float* w2b = (const float*)d_in[8];
    const float* b2b = (const float*)d_in[9];
    const float* w3  = (const float*)d_in[10];
    const float* b3  = (const float*)d_in[11];

    int nN = in_sizes[0] / 128;
    int nE = in_sizes[1] / 2;
    float* out = (float*)d_out;

    // dtype detect + weight folding (W12, b12, w23, c23)
    k_init<<<1, 1024>>>(ei, 2 * nE, w1b, b1b, w2a, w2b, b2b, w3);
    // conv1: project 128->32 first (aggregation commutes with the linear map)
    k_proj1<<<4736, 128>>>(x, w1a, nN);
    k_edge32<<<((size_t)nE * 8 + 255) / 256, 256>>>(ei, nE, 0);
    // conv1 MLP tail folded with conv2 first linear: one 32x32 GEMM per node
    k_mlp1<<<1184, 256>>>(b1a, nN);
    k_edge32<<<((size_t)nE * 8 + 255) / 256, 256>>>(ei, nE, 1);
    // conv2 MLP tail folded with conv3 linear: dot product per node
    k_mlp2<<<1184, 256>>>(b2a, b3, out, nN);
    k_edge1<<<(nE + 255) / 256, 256>>>(ei, nE, out);
}